// round 11
// baseline (speedup 1.0000x reference)
#include <cuda_runtime.h>

// Perona-Malik diffusion, 3 iterations fused in ONE kernel.
// Warp-register temporal pipeline (6 stages), 4 cols/lane via float4,
// horizontal via shuffles, vertical via register sliding window.
// R10 base (grouped reciprocal, 2-shuffle divergence, one-wave scheduling).
// R11: occupancy push - __launch_bounds__(128,5) caps regs at 102 so 5
// blocks/SM fit the RF; work re-split to CHUNK=58 x 18 bands = 2880 warps
// = 720 blocks <= 740 single-wave slots -> 19.5 warps/SM (+29%).

#define NB 16
#define H  1024
#define W  1024

#define HALO   8
#define OUTWC  112
#define NSTRIP 10
#define CHUNK  58
#define NBANDS 18     // 18*58 = 1044 >= 1024 (last band stores 38 rows)

#define K2_64  0.16f            // 64 * kappa^2
#define K2E    0.16000064f      // 64 * (kappa^2 + eps)
#define DTC    0.00390625f      // DT / 64

__device__ __forceinline__ float4 mk4(float v) { return make_float4(v, v, v, v); }

struct Flux { float4 fx, fy; };

// flux (scaled by 8) at one row from input rows vm, vc, vp.
__device__ __forceinline__ Flux fluxrow(const float4 vm, const float4 vc,
                                        const float4 vp, const bool valid)
{
    const unsigned m = 0xffffffffu;
    const float a0 = vm.x + 2.f*vc.x + vp.x;
    const float a1 = vm.y + 2.f*vc.y + vp.y;
    const float a2 = vm.z + 2.f*vc.z + vp.z;
    const float a3 = vm.w + 2.f*vc.w + vp.w;
    const float b0 = vp.x - vm.x;
    const float b1 = vp.y - vm.y;
    const float b2 = vp.z - vm.z;
    const float b3 = vp.w - vm.w;
    const float aL = __shfl_up_sync(m, a3, 1);
    const float aR = __shfl_down_sync(m, a0, 1);
    const float bL = __shfl_up_sync(m, b3, 1);
    const float bR = __shfl_down_sync(m, b0, 1);
    const float gx0 = a1 - aL;                 // 8*gx
    const float gx1 = a2 - a0;
    const float gx2 = a3 - a1;
    const float gx3 = aR - a2;
    const float gy0 = bL + 2.f*b0 + b1;        // 8*gy
    const float gy1 = b0 + 2.f*b1 + b2;
    const float gy2 = b1 + 2.f*b2 + b3;
    const float gy3 = b2 + 2.f*b3 + bR;
    const float d0 = fmaf(gx0, gx0, fmaf(gy0, gy0, K2E));
    const float d1 = fmaf(gx1, gx1, fmaf(gy1, gy1, K2E));
    const float d2 = fmaf(gx2, gx2, fmaf(gy2, gy2, K2E));
    const float d3 = fmaf(gx3, gx3, fmaf(gy3, gy3, K2E));

    // grouped reciprocal: one RCP for four conduction coefficients.
    const float d01  = d0 * d1;
    const float d23  = d2 * d3;
    const float invK = __fdividef(K2_64, d01 * d23);
    float c0 = (d1 * d23) * invK;
    float c1 = (d0 * d23) * invK;
    float c2 = (d01 * d3) * invK;
    float c3 = (d01 * d2) * invK;
    c0 = valid ? c0 : 0.f;
    c1 = valid ? c1 : 0.f;
    c2 = valid ? c2 : 0.f;
    c3 = valid ? c3 : 0.f;

    Flux f;
    f.fx = make_float4(c0*gx0, c1*gx1, c2*gx2, c3*gx3);   // 8*flux
    f.fy = make_float4(c0*gy0, c1*gy1, c2*gy2, c3*gy3);
    return f;
}

// out = base + (DT/64) * dsum8; u/v identity -> only 2 shuffles.
__device__ __forceinline__ float4 updrow(const float4 base,
                                         const Flux f0, const Flux f1,
                                         const Flux f2, const bool valid)
{
    const unsigned m = 0xffffffffu;
    const float p0 = f0.fx.x + 2.f*f1.fx.x + f2.fx.x;
    const float p1 = f0.fx.y + 2.f*f1.fx.y + f2.fx.y;
    const float p2 = f0.fx.z + 2.f*f1.fx.z + f2.fx.z;
    const float p3 = f0.fx.w + 2.f*f1.fx.w + f2.fx.w;
    const float q0 = f2.fy.x - f0.fy.x;
    const float q1 = f2.fy.y - f0.fy.y;
    const float q2 = f2.fy.z - f0.fy.z;
    const float q3 = f2.fy.w - f0.fy.w;

    const float u0 = p0 + q0, u1 = p1 + q1, u2 = p2 + q2, u3 = p3 + q3;
    const float v0 = q0 - p0, v1 = q1 - p1, v2 = q2 - p2, v3 = q3 - p3;

    const float vL = __shfl_up_sync(m, v3, 1);
    const float uR = __shfl_down_sync(m, u0, 1);

    const float d0 = fmaf(2.f, q0, vL) + u1;
    const float d1 = fmaf(2.f, q1, v0) + u2;
    const float d2 = fmaf(2.f, q2, v1) + u3;
    const float d3 = fmaf(2.f, q3, v2) + uR;

    float4 o;
    o.x = valid ? fmaf(DTC, d0, base.x) : 0.f;
    o.y = valid ? fmaf(DTC, d1, base.y) : 0.f;
    o.z = valid ? fmaf(DTC, d2, base.z) : 0.f;
    o.w = valid ? fmaf(DTC, d3, base.w) : 0.f;
    return o;
}

// GUARD=true: boundary warps, full predication, variable rows.
// GUARD=false: fully interior warps, no checks, compile-time row count.
template<bool GUARD>
__device__ __forceinline__ void run_strip(const float* __restrict__ img,
                                          float* __restrict__ op,
                                          const int x0, const int y0,
                                          const int nrows,
                                          const bool colv, const bool st_ok)
{
    const float* lp = img + (size_t)(y0 - 6) * W + x0;   // next row to load
    float*       sp = op  + (size_t)y0 * W + x0;         // next row to store

    int ly = y0 - 6;
    auto load = [&]() -> float4 {
        float4 v;
        if (GUARD) {
            v = (colv && (unsigned)ly < (unsigned)H)
                    ? __ldg(reinterpret_cast<const float4*>(lp)) : mk4(0.f);
            ++ly;
        } else {
            v = __ldg(reinterpret_cast<const float4*>(lp));
        }
        lp += W;
        return v;
    };
    auto rv = [&](int y) -> bool {
        return GUARD ? (colv && (unsigned)y < (unsigned)H) : true;
    };

    float4 i0 = load();
    float4 i1 = load();
    float4 i2 = load();

    Flux zf; zf.fx = mk4(0.f); zf.fy = mk4(0.f);
    Flux  f1a = zf, f1b = zf, f2a = zf, f2b = zf, f3a = zf, f3b = zf;
    float4 o1a = mk4(0.f), o1b = o1a, o2a = o1a, o2b = o1a;

    auto step = [&](int y) -> float4 {
        const float4 inext = load();
        const Flux   f1c = fluxrow(i0, i1, i2,         rv(y + 5));
        const float4 o1c = updrow (i0, f1a, f1b, f1c,  rv(y + 4));
        const Flux   f2c = fluxrow(o1a, o1b, o1c,      rv(y + 3));
        const float4 o2c = updrow (o1a, f2a, f2b, f2c, rv(y + 2));
        const Flux   f3c = fluxrow(o2a, o2b, o2c,      rv(y + 1));
        const float4 o3  = updrow (o2a, f3a, f3b, f3c, rv(y));
        i0 = i1; i1 = i2; i2 = inext;
        f1a = f1b; f1b = f1c;
        o1a = o1b; o1b = o1c;
        f2a = f2b; f2b = f2c;
        o2a = o2b; o2b = o2c;
        f3a = f3b; f3b = f3c;
        return o3;
    };

    // warm-up: 10 steps, nothing stored
    #pragma unroll 2
    for (int y = y0 - 10; y < y0; ++y)
        (void)step(y);

    if (GUARD) {
        for (int y = y0; y < y0 + nrows; ++y) {
            const float4 o3 = step(y);
            if (st_ok)
                *reinterpret_cast<float4*>(sp) = o3;
            sp += W;
        }
    } else {
        #pragma unroll 2
        for (int y = y0; y < y0 + CHUNK; ++y) {
            const float4 o3 = step(y);
            if (st_ok)
                *reinterpret_cast<float4*>(sp) = o3;
            sp += W;
        }
    }
}

__global__ __launch_bounds__(128, 5)       // cap ~102 regs -> 5 blocks/SM
void pm_fused3(const float* __restrict__ in, float* __restrict__ out)
{
    const int lane = threadIdx.x & 31;
    const int warp = threadIdx.x >> 5;

    // flattened work item: 10 strips x 18 bands x 16 images = 2880 warps
    const int item  = blockIdx.x * 4 + warp;
    const int image = item / (NSTRIP * NBANDS);
    const int rem   = item - image * (NSTRIP * NBANDS);
    const int strip = rem / NBANDS;
    const int band  = rem - strip * NBANDS;

    const int x0 = strip * OUTWC - HALO + lane * 4;
    const int y0 = band * CHUNK;
    const int nrows = (band == NBANDS - 1) ? (H - y0) : CHUNK;   // 38 or 58

    const size_t plane = (size_t)image * (size_t)(H * W);
    const float* __restrict__ img = in  + plane;
    float*       __restrict__ op  = out + plane;

    const bool colv  = (x0 >= 0) && (x0 + 4 <= W);
    const bool st_ok = colv && (lane >= HALO / 4) && (lane < 32 - HALO / 4);

    const bool interior = (strip >= 1) && (strip <= NSTRIP - 2) &&
                          (band >= 1) && (y0 + CHUNK + 6 < H);

    if (interior)
        run_strip<false>(img, op, x0, y0, CHUNK, true, st_ok);
    else
        run_strip<true>(img, op, x0, y0, nrows, colv, st_ok);
}

extern "C" void kernel_launch(void* const* d_in, const int* in_sizes, int n_in,
                              void* d_out, int out_size)
{
    const float* image = (const float*)d_in[0];
    float* out = (float*)d_out;

    // 2880 work items / 4 warps per block = 720 blocks: exactly one wave
    // at 5 blocks/SM residency (740 slots on 148 SMs).
    pm_fused3<<<720, 128>>>(image, out);
}

// round 12
// speedup vs baseline: 1.0028x; 1.0028x over previous
#include <cuda_runtime.h>

// Perona-Malik diffusion, 3 iterations fused in ONE kernel.
// Warp-register temporal pipeline (6 stages), 4 cols/lane via float4,
// horizontal via shuffles, vertical via register sliding window.
// R10 base (grouped reciprocal, 2-shuffle divergence, one-wave scheduling).
// R11: occupancy push - __launch_bounds__(128,5) caps regs at 102 so 5
// blocks/SM fit the RF; work re-split to CHUNK=58 x 18 bands = 2880 warps
// = 720 blocks <= 740 single-wave slots -> 19.5 warps/SM (+29%).

#define NB 16
#define H  1024
#define W  1024

#define HALO   8
#define OUTWC  112
#define NSTRIP 10
#define CHUNK  58
#define NBANDS 18     // 18*58 = 1044 >= 1024 (last band stores 38 rows)

#define K2_64  0.16f            // 64 * kappa^2
#define K2E    0.16000064f      // 64 * (kappa^2 + eps)
#define DTC    0.00390625f      // DT / 64

__device__ __forceinline__ float4 mk4(float v) { return make_float4(v, v, v, v); }

struct Flux { float4 fx, fy; };

// flux (scaled by 8) at one row from input rows vm, vc, vp.
__device__ __forceinline__ Flux fluxrow(const float4 vm, const float4 vc,
                                        const float4 vp, const bool valid)
{
    const unsigned m = 0xffffffffu;
    const float a0 = vm.x + 2.f*vc.x + vp.x;
    const float a1 = vm.y + 2.f*vc.y + vp.y;
    const float a2 = vm.z + 2.f*vc.z + vp.z;
    const float a3 = vm.w + 2.f*vc.w + vp.w;
    const float b0 = vp.x - vm.x;
    const float b1 = vp.y - vm.y;
    const float b2 = vp.z - vm.z;
    const float b3 = vp.w - vm.w;
    const float aL = __shfl_up_sync(m, a3, 1);
    const float aR = __shfl_down_sync(m, a0, 1);
    const float bL = __shfl_up_sync(m, b3, 1);
    const float bR = __shfl_down_sync(m, b0, 1);
    const float gx0 = a1 - aL;                 // 8*gx
    const float gx1 = a2 - a0;
    const float gx2 = a3 - a1;
    const float gx3 = aR - a2;
    const float gy0 = bL + 2.f*b0 + b1;        // 8*gy
    const float gy1 = b0 + 2.f*b1 + b2;
    const float gy2 = b1 + 2.f*b2 + b3;
    const float gy3 = b2 + 2.f*b3 + bR;
    const float d0 = fmaf(gx0, gx0, fmaf(gy0, gy0, K2E));
    const float d1 = fmaf(gx1, gx1, fmaf(gy1, gy1, K2E));
    const float d2 = fmaf(gx2, gx2, fmaf(gy2, gy2, K2E));
    const float d3 = fmaf(gx3, gx3, fmaf(gy3, gy3, K2E));

    // grouped reciprocal: one RCP for four conduction coefficients.
    const float d01  = d0 * d1;
    const float d23  = d2 * d3;
    const float invK = __fdividef(K2_64, d01 * d23);
    float c0 = (d1 * d23) * invK;
    float c1 = (d0 * d23) * invK;
    float c2 = (d01 * d3) * invK;
    float c3 = (d01 * d2) * invK;
    c0 = valid ? c0 : 0.f;
    c1 = valid ? c1 : 0.f;
    c2 = valid ? c2 : 0.f;
    c3 = valid ? c3 : 0.f;

    Flux f;
    f.fx = make_float4(c0*gx0, c1*gx1, c2*gx2, c3*gx3);   // 8*flux
    f.fy = make_float4(c0*gy0, c1*gy1, c2*gy2, c3*gy3);
    return f;
}

// out = base + (DT/64) * dsum8; u/v identity -> only 2 shuffles.
__device__ __forceinline__ float4 updrow(const float4 base,
                                         const Flux f0, const Flux f1,
                                         const Flux f2, const bool valid)
{
    const unsigned m = 0xffffffffu;
    const float p0 = f0.fx.x + 2.f*f1.fx.x + f2.fx.x;
    const float p1 = f0.fx.y + 2.f*f1.fx.y + f2.fx.y;
    const float p2 = f0.fx.z + 2.f*f1.fx.z + f2.fx.z;
    const float p3 = f0.fx.w + 2.f*f1.fx.w + f2.fx.w;
    const float q0 = f2.fy.x - f0.fy.x;
    const float q1 = f2.fy.y - f0.fy.y;
    const float q2 = f2.fy.z - f0.fy.z;
    const float q3 = f2.fy.w - f0.fy.w;

    const float u0 = p0 + q0, u1 = p1 + q1, u2 = p2 + q2, u3 = p3 + q3;
    const float v0 = q0 - p0, v1 = q1 - p1, v2 = q2 - p2, v3 = q3 - p3;

    const float vL = __shfl_up_sync(m, v3, 1);
    const float uR = __shfl_down_sync(m, u0, 1);

    const float d0 = fmaf(2.f, q0, vL) + u1;
    const float d1 = fmaf(2.f, q1, v0) + u2;
    const float d2 = fmaf(2.f, q2, v1) + u3;
    const float d3 = fmaf(2.f, q3, v2) + uR;

    float4 o;
    o.x = valid ? fmaf(DTC, d0, base.x) : 0.f;
    o.y = valid ? fmaf(DTC, d1, base.y) : 0.f;
    o.z = valid ? fmaf(DTC, d2, base.z) : 0.f;
    o.w = valid ? fmaf(DTC, d3, base.w) : 0.f;
    return o;
}

// GUARD=true: boundary warps, full predication, variable rows.
// GUARD=false: fully interior warps, no checks, compile-time row count.
template<bool GUARD>
__device__ __forceinline__ void run_strip(const float* __restrict__ img,
                                          float* __restrict__ op,
                                          const int x0, const int y0,
                                          const int nrows,
                                          const bool colv, const bool st_ok)
{
    const float* lp = img + (size_t)(y0 - 6) * W + x0;   // next row to load
    float*       sp = op  + (size_t)y0 * W + x0;         // next row to store

    int ly = y0 - 6;
    auto load = [&]() -> float4 {
        float4 v;
        if (GUARD) {
            v = (colv && (unsigned)ly < (unsigned)H)
                    ? __ldg(reinterpret_cast<const float4*>(lp)) : mk4(0.f);
            ++ly;
        } else {
            v = __ldg(reinterpret_cast<const float4*>(lp));
        }
        lp += W;
        return v;
    };
    auto rv = [&](int y) -> bool {
        return GUARD ? (colv && (unsigned)y < (unsigned)H) : true;
    };

    float4 i0 = load();
    float4 i1 = load();
    float4 i2 = load();

    Flux zf; zf.fx = mk4(0.f); zf.fy = mk4(0.f);
    Flux  f1a = zf, f1b = zf, f2a = zf, f2b = zf, f3a = zf, f3b = zf;
    float4 o1a = mk4(0.f), o1b = o1a, o2a = o1a, o2b = o1a;

    auto step = [&](int y) -> float4 {
        const float4 inext = load();
        const Flux   f1c = fluxrow(i0, i1, i2,         rv(y + 5));
        const float4 o1c = updrow (i0, f1a, f1b, f1c,  rv(y + 4));
        const Flux   f2c = fluxrow(o1a, o1b, o1c,      rv(y + 3));
        const float4 o2c = updrow (o1a, f2a, f2b, f2c, rv(y + 2));
        const Flux   f3c = fluxrow(o2a, o2b, o2c,      rv(y + 1));
        const float4 o3  = updrow (o2a, f3a, f3b, f3c, rv(y));
        i0 = i1; i1 = i2; i2 = inext;
        f1a = f1b; f1b = f1c;
        o1a = o1b; o1b = o1c;
        f2a = f2b; f2b = f2c;
        o2a = o2b; o2b = o2c;
        f3a = f3b; f3b = f3c;
        return o3;
    };

    // warm-up: 10 steps, nothing stored
    #pragma unroll 2
    for (int y = y0 - 10; y < y0; ++y)
        (void)step(y);

    if (GUARD) {
        for (int y = y0; y < y0 + nrows; ++y) {
            const float4 o3 = step(y);
            if (st_ok)
                *reinterpret_cast<float4*>(sp) = o3;
            sp += W;
        }
    } else {
        #pragma unroll 2
        for (int y = y0; y < y0 + CHUNK; ++y) {
            const float4 o3 = step(y);
            if (st_ok)
                *reinterpret_cast<float4*>(sp) = o3;
            sp += W;
        }
    }
}

__global__ __launch_bounds__(128, 5)       // cap ~102 regs -> 5 blocks/SM
void pm_fused3(const float* __restrict__ in, float* __restrict__ out)
{
    const int lane = threadIdx.x & 31;
    const int warp = threadIdx.x >> 5;

    // flattened work item: 10 strips x 18 bands x 16 images = 2880 warps
    const int item  = blockIdx.x * 4 + warp;
    const int image = item / (NSTRIP * NBANDS);
    const int rem   = item - image * (NSTRIP * NBANDS);
    const int strip = rem / NBANDS;
    const int band  = rem - strip * NBANDS;

    const int x0 = strip * OUTWC - HALO + lane * 4;
    const int y0 = band * CHUNK;
    const int nrows = (band == NBANDS - 1) ? (H - y0) : CHUNK;   // 38 or 58

    const size_t plane = (size_t)image * (size_t)(H * W);
    const float* __restrict__ img = in  + plane;
    float*       __restrict__ op  = out + plane;

    const bool colv  = (x0 >= 0) && (x0 + 4 <= W);
    const bool st_ok = colv && (lane >= HALO / 4) && (lane < 32 - HALO / 4);

    const bool interior = (strip >= 1) && (strip <= NSTRIP - 2) &&
                          (band >= 1) && (y0 + CHUNK + 6 < H);

    if (interior)
        run_strip<false>(img, op, x0, y0, CHUNK, true, st_ok);
    else
        run_strip<true>(img, op, x0, y0, nrows, colv, st_ok);
}

extern "C" void kernel_launch(void* const* d_in, const int* in_sizes, int n_in,
                              void* d_out, int out_size)
{
    const float* image = (const float*)d_in[0];
    float* out = (float*)d_out;

    // 2880 work items / 4 warps per block = 720 blocks: exactly one wave
    // at 5 blocks/SM residency (740 slots on 148 SMs).
    pm_fused3<<<720, 128>>>(image, out);
}

// round 13
// speedup vs baseline: 1.1664x; 1.1632x over previous
#include <cuda_runtime.h>

// Perona-Malik diffusion, 3 iterations fused in ONE kernel.
// Warp-register temporal pipeline (6 stages), 4 cols/lane via float4,
// horizontal via shuffles, vertical via register sliding window.
// R10 base: grouped reciprocal (1 RCP/flux row), 2-shuffle divergence,
// exactly-one-wave scheduling (2240 warp-strips, 560 blocks, 128-reg cap).
// (R11's 5-block occupancy push spilled and regressed - reverted.)
// R12: cross-step ILP - unroll 4 on the interior main loop + fully unrolled
// warm-up + 2-row load prefetch so ptxas can overlap pipeline stages of
// adjacent steps and fill the ~28% idle issue slots.

#define NB 16
#define H  1024
#define W  1024

#define HALO   8
#define OUTWC  112
#define NSTRIP 10
#define CHUNK  74
#define NBANDS 14     // 14*74 = 1036 >= 1024 (last band stores 62 rows)

#define K2_64  0.16f            // 64 * kappa^2
#define K2E    0.16000064f      // 64 * (kappa^2 + eps)
#define DTC    0.00390625f      // DT / 64

__device__ __forceinline__ float4 mk4(float v) { return make_float4(v, v, v, v); }

struct Flux { float4 fx, fy; };

// flux (scaled by 8) at one row from input rows vm, vc, vp.
__device__ __forceinline__ Flux fluxrow(const float4 vm, const float4 vc,
                                        const float4 vp, const bool valid)
{
    const unsigned m = 0xffffffffu;
    const float a0 = vm.x + 2.f*vc.x + vp.x;
    const float a1 = vm.y + 2.f*vc.y + vp.y;
    const float a2 = vm.z + 2.f*vc.z + vp.z;
    const float a3 = vm.w + 2.f*vc.w + vp.w;
    const float b0 = vp.x - vm.x;
    const float b1 = vp.y - vm.y;
    const float b2 = vp.z - vm.z;
    const float b3 = vp.w - vm.w;
    const float aL = __shfl_up_sync(m, a3, 1);
    const float aR = __shfl_down_sync(m, a0, 1);
    const float bL = __shfl_up_sync(m, b3, 1);
    const float bR = __shfl_down_sync(m, b0, 1);
    const float gx0 = a1 - aL;                 // 8*gx
    const float gx1 = a2 - a0;
    const float gx2 = a3 - a1;
    const float gx3 = aR - a2;
    const float gy0 = bL + 2.f*b0 + b1;        // 8*gy
    const float gy1 = b0 + 2.f*b1 + b2;
    const float gy2 = b1 + 2.f*b2 + b3;
    const float gy3 = b2 + 2.f*b3 + bR;
    const float d0 = fmaf(gx0, gx0, fmaf(gy0, gy0, K2E));
    const float d1 = fmaf(gx1, gx1, fmaf(gy1, gy1, K2E));
    const float d2 = fmaf(gx2, gx2, fmaf(gy2, gy2, K2E));
    const float d3 = fmaf(gx3, gx3, fmaf(gy3, gy3, K2E));

    // grouped reciprocal: one RCP for four conduction coefficients.
    const float d01  = d0 * d1;
    const float d23  = d2 * d3;
    const float invK = __fdividef(K2_64, d01 * d23);
    float c0 = (d1 * d23) * invK;
    float c1 = (d0 * d23) * invK;
    float c2 = (d01 * d3) * invK;
    float c3 = (d01 * d2) * invK;
    c0 = valid ? c0 : 0.f;
    c1 = valid ? c1 : 0.f;
    c2 = valid ? c2 : 0.f;
    c3 = valid ? c3 : 0.f;

    Flux f;
    f.fx = make_float4(c0*gx0, c1*gx1, c2*gx2, c3*gx3);   // 8*flux
    f.fy = make_float4(c0*gy0, c1*gy1, c2*gy2, c3*gy3);
    return f;
}

// out = base + (DT/64) * dsum8; u/v identity -> only 2 shuffles.
__device__ __forceinline__ float4 updrow(const float4 base,
                                         const Flux f0, const Flux f1,
                                         const Flux f2, const bool valid)
{
    const unsigned m = 0xffffffffu;
    const float p0 = f0.fx.x + 2.f*f1.fx.x + f2.fx.x;
    const float p1 = f0.fx.y + 2.f*f1.fx.y + f2.fx.y;
    const float p2 = f0.fx.z + 2.f*f1.fx.z + f2.fx.z;
    const float p3 = f0.fx.w + 2.f*f1.fx.w + f2.fx.w;
    const float q0 = f2.fy.x - f0.fy.x;
    const float q1 = f2.fy.y - f0.fy.y;
    const float q2 = f2.fy.z - f0.fy.z;
    const float q3 = f2.fy.w - f0.fy.w;

    const float u0 = p0 + q0, u1 = p1 + q1, u2 = p2 + q2, u3 = p3 + q3;
    const float v0 = q0 - p0, v1 = q1 - p1, v2 = q2 - p2, v3 = q3 - p3;

    const float vL = __shfl_up_sync(m, v3, 1);
    const float uR = __shfl_down_sync(m, u0, 1);

    const float d0 = fmaf(2.f, q0, vL) + u1;
    const float d1 = fmaf(2.f, q1, v0) + u2;
    const float d2 = fmaf(2.f, q2, v1) + u3;
    const float d3 = fmaf(2.f, q3, v2) + uR;

    float4 o;
    o.x = valid ? fmaf(DTC, d0, base.x) : 0.f;
    o.y = valid ? fmaf(DTC, d1, base.y) : 0.f;
    o.z = valid ? fmaf(DTC, d2, base.z) : 0.f;
    o.w = valid ? fmaf(DTC, d3, base.w) : 0.f;
    return o;
}

// GUARD=true: boundary warps, full predication, variable rows.
// GUARD=false: fully interior warps, no checks, compile-time row count.
template<bool GUARD>
__device__ __forceinline__ void run_strip(const float* __restrict__ img,
                                          float* __restrict__ op,
                                          const int x0, const int y0,
                                          const int nrows,
                                          const bool colv, const bool st_ok)
{
    const float* lp = img + (size_t)(y0 - 6) * W + x0;   // next row to load
    float*       sp = op  + (size_t)y0 * W + x0;         // next row to store

    int ly = y0 - 6;
    auto load = [&]() -> float4 {
        float4 v;
        if (GUARD) {
            v = (colv && (unsigned)ly < (unsigned)H)
                    ? __ldg(reinterpret_cast<const float4*>(lp)) : mk4(0.f);
            ++ly;
        } else {
            v = __ldg(reinterpret_cast<const float4*>(lp));
        }
        lp += W;
        return v;
    };
    auto rv = [&](int y) -> bool {
        return GUARD ? (colv && (unsigned)y < (unsigned)H) : true;
    };

    // 2-ahead load prefetch: i0..i2 window + i3 in flight
    float4 i0 = load();
    float4 i1 = load();
    float4 i2 = load();
    float4 i3 = load();

    Flux zf; zf.fx = mk4(0.f); zf.fy = mk4(0.f);
    Flux  f1a = zf, f1b = zf, f2a = zf, f2b = zf, f3a = zf, f3b = zf;
    float4 o1a = mk4(0.f), o1b = o1a, o2a = o1a, o2b = o1a;

    auto step = [&](int y) -> float4 {
        const float4 inext = load();              // 2 rows ahead of use
        const Flux   f1c = fluxrow(i0, i1, i2,         rv(y + 5));
        const float4 o1c = updrow (i0, f1a, f1b, f1c,  rv(y + 4));
        const Flux   f2c = fluxrow(o1a, o1b, o1c,      rv(y + 3));
        const float4 o2c = updrow (o1a, f2a, f2b, f2c, rv(y + 2));
        const Flux   f3c = fluxrow(o2a, o2b, o2c,      rv(y + 1));
        const float4 o3  = updrow (o2a, f3a, f3b, f3c, rv(y));
        i0 = i1; i1 = i2; i2 = i3; i3 = inext;
        f1a = f1b; f1b = f1c;
        o1a = o1b; o1b = o1c;
        f2a = f2b; f2b = f2c;
        o2a = o2b; o2b = o2c;
        f3a = f3b; f3b = f3c;
        return o3;
    };

    // warm-up: 10 steps, nothing stored (fully unrolled)
    #pragma unroll
    for (int k = 0; k < 10; ++k)
        (void)step(y0 - 10 + k);

    if (GUARD) {
        #pragma unroll 2
        for (int y = y0; y < y0 + nrows; ++y) {
            const float4 o3 = step(y);
            if (st_ok)
                *reinterpret_cast<float4*>(sp) = o3;
            sp += W;
        }
    } else {
        // interior: wide unroll so ptxas can overlap stages across steps
        #pragma unroll 4
        for (int y = y0; y < y0 + CHUNK; ++y) {
            const float4 o3 = step(y);
            if (st_ok)
                *reinterpret_cast<float4*>(sp) = o3;
            sp += W;
        }
    }
}

__global__ __launch_bounds__(128, 4)       // cap 128 regs -> 4 blocks/SM
void pm_fused3(const float* __restrict__ in, float* __restrict__ out)
{
    const int lane = threadIdx.x & 31;
    const int warp = threadIdx.x >> 5;

    // flattened work item: 10 strips x 14 bands x 16 images = 2240 warps
    const int item  = blockIdx.x * 4 + warp;
    const int image = item / (NSTRIP * NBANDS);
    const int rem   = item - image * (NSTRIP * NBANDS);
    const int strip = rem / NBANDS;
    const int band  = rem - strip * NBANDS;

    const int x0 = strip * OUTWC - HALO + lane * 4;
    const int y0 = band * CHUNK;
    const int nrows = (band == NBANDS - 1) ? (H - y0) : CHUNK;   // 62 or 74

    const size_t plane = (size_t)image * (size_t)(H * W);
    const float* __restrict__ img = in  + plane;
    float*       __restrict__ op  = out + plane;

    const bool colv  = (x0 >= 0) && (x0 + 4 <= W);
    const bool st_ok = colv && (lane >= HALO / 4) && (lane < 32 - HALO / 4);

    const bool interior = (strip >= 1) && (strip <= NSTRIP - 2) &&
                          (band >= 1) && (y0 + CHUNK + 7 < H);

    if (interior)
        run_strip<false>(img, op, x0, y0, CHUNK, true, st_ok);
    else
        run_strip<true>(img, op, x0, y0, nrows, colv, st_ok);
}

extern "C" void kernel_launch(void* const* d_in, const int* in_sizes, int n_in,
                              void* d_out, int out_size)
{
    const float* image = (const float*)d_in[0];
    float* out = (float*)d_out;

    // 2240 work items / 4 warps per block = 560 blocks: exactly one wave
    // at 4 blocks/SM residency (592 slots on 148 SMs).
    pm_fused3<<<560, 128>>>(image, out);
}